// round 1
// baseline (speedup 1.0000x reference)
#include <cuda_runtime.h>
#include <cstddef>

// Problem constants (shapes fixed for this problem instance)
#define NMAX 100000
#define F    128      // in/out feature dim
#define K2   256      // concat dim = 2*F
#define NT   32       // nodes per block in fused kernel

// ---------------- scratch (allocation-free: __device__ globals) ------------
__device__ float g_msg[(size_t)NMAX * F];   // 51.2 MB message sums
__device__ float g_deg[NMAX];               // in-degree (float)
__device__ float g_Wt[K2 * F];              // W transposed: Wt[k][j] = W[j][k]

// ---------------- kernel 1: transpose W (tiny) ------------------------------
__global__ void transpose_w(const float* __restrict__ W) {
    int k = blockIdx.x;     // 0..255
    int j = threadIdx.x;    // 0..127
    g_Wt[k * F + j] = W[j * K2 + k];
}

// ---------------- kernel 2: edge scatter (mean numerator + degree) ----------
// One warp per edge. Lane l handles floats [4l..4l+3] of the 128-wide row.
__global__ void edge_scatter(const float* __restrict__ h,
                             const int*   __restrict__ src,
                             const int*   __restrict__ dst,
                             int E) {
    int e    = (int)((blockIdx.x * (size_t)blockDim.x + threadIdx.x) >> 5);
    int lane = threadIdx.x & 31;
    if (e >= E) return;
    int s = __ldg(src + e);
    int d = __ldg(dst + e);
    const float4 v = *reinterpret_cast<const float4*>(h + (size_t)s * F + lane * 4);
    float* p = g_msg + (size_t)d * F + lane * 4;
    // sm_90+ vector float reduction (no return value): 1 instr per 16B
    asm volatile("red.global.add.v4.f32 [%0], {%1, %2, %3, %4};"
                 :: "l"(p), "f"(v.x), "f"(v.y), "f"(v.z), "f"(v.w)
                 : "memory");
    if (lane == 0) atomicAdd(g_deg + d, 1.0f);
}

// ---------------- kernel 3: fused mean + concat-GEMM + LN + ReLU ------------
// Block: 256 threads, NT=32 nodes. Thread (tx,ty): tx=lane (0..31) owns output
// cols j0=4*tx..4*tx+3; ty=warp (0..7) owns node group n0=4*ty..4*ty+3.
// Each warp covers a full 128-wide output row for its 4 nodes -> LN via shfl.
__global__ __launch_bounds__(256)
void fused_node(const float* __restrict__ h,
                const float* __restrict__ bias,
                const float* __restrict__ gamma,
                const float* __restrict__ beta,
                float* __restrict__ out,
                int N) {
    __shared__ float xs[NT][K2];      // 32 KB: concat[h, mean_agg]
    __shared__ float rdeg_s[NT];

    const int tid   = threadIdx.x;
    const int node0 = blockIdx.x * NT;
    const int nval  = min(NT, N - node0);

    if (tid < NT) {
        float dg = (tid < nval) ? g_deg[node0 + tid] : 1.0f;
        rdeg_s[tid] = 1.0f / fmaxf(dg, 1.0f);
    }
    __syncthreads();

    // stage x = [h | msg/deg] into shared, coalesced over k
    #pragma unroll
    for (int idx = tid; idx < NT * K2; idx += 256) {
        int n = idx >> 8;        // node within tile
        int k = idx & 255;
        float v = 0.0f;
        if (n < nval) {
            size_t row = (size_t)(node0 + n) * F;
            if (k < F) v = h[row + k];
            else       v = g_msg[row + (k - F)] * rdeg_s[n];
        }
        xs[n][k] = v;
    }
    __syncthreads();

    const int tx = tid & 31;
    const int ty = tid >> 5;
    const int j0 = tx * 4;
    const int n0 = ty * 4;

    float acc[4][4];
    #pragma unroll
    for (int i = 0; i < 4; i++)
        #pragma unroll
        for (int c = 0; c < 4; c++) acc[i][c] = 0.0f;

    // main GEMM loop: 16 FMA + 4 LDS(broadcast) + 1 LDG.128(L1-hot Wt) per k
    #pragma unroll 4
    for (int k = 0; k < K2; k++) {
        const float4 w = *reinterpret_cast<const float4*>(g_Wt + k * F + j0);
        #pragma unroll
        for (int i = 0; i < 4; i++) {
            float x = xs[n0 + i][k];
            acc[i][0] = fmaf(x, w.x, acc[i][0]);
            acc[i][1] = fmaf(x, w.y, acc[i][1]);
            acc[i][2] = fmaf(x, w.z, acc[i][2]);
            acc[i][3] = fmaf(x, w.w, acc[i][3]);
        }
    }

    // epilogue: +bias, LayerNorm over 128 outputs (warp reduce), affine, ReLU
    const float4 bb = *reinterpret_cast<const float4*>(bias  + j0);
    const float4 gg = *reinterpret_cast<const float4*>(gamma + j0);
    const float4 be = *reinterpret_cast<const float4*>(beta  + j0);

    #pragma unroll
    for (int i = 0; i < 4; i++) {
        float z0 = acc[i][0] + bb.x;
        float z1 = acc[i][1] + bb.y;
        float z2 = acc[i][2] + bb.z;
        float z3 = acc[i][3] + bb.w;

        float s = z0 + z1 + z2 + z3;
        #pragma unroll
        for (int o = 16; o > 0; o >>= 1) s += __shfl_xor_sync(0xFFFFFFFFu, s, o);
        const float mu = s * (1.0f / 128.0f);

        float d0 = z0 - mu, d1 = z1 - mu, d2 = z2 - mu, d3 = z3 - mu;
        float q = d0 * d0 + d1 * d1 + d2 * d2 + d3 * d3;
        #pragma unroll
        for (int o = 16; o > 0; o >>= 1) q += __shfl_xor_sync(0xFFFFFFFFu, q, o);
        const float inv = rsqrtf(q * (1.0f / 128.0f) + 1e-5f);

        float4 r;
        r.x = fmaxf(d0 * inv * gg.x + be.x, 0.0f);
        r.y = fmaxf(d1 * inv * gg.y + be.y, 0.0f);
        r.z = fmaxf(d2 * inv * gg.z + be.z, 0.0f);
        r.w = fmaxf(d3 * inv * gg.w + be.w, 0.0f);

        int n = node0 + n0 + i;
        if (n0 + i < nval)
            *reinterpret_cast<float4*>(out + (size_t)n * F + j0) = r;
    }
}

// ---------------- launch ----------------------------------------------------
extern "C" void kernel_launch(void* const* d_in, const int* in_sizes, int n_in,
                              void* d_out, int out_size) {
    const float* h     = (const float*)d_in[0];
    const int*   src   = (const int*)  d_in[1];
    const int*   dst   = (const int*)  d_in[2];
    const float* W     = (const float*)d_in[3];
    const float* bias  = (const float*)d_in[4];
    const float* gamma = (const float*)d_in[5];
    const float* beta  = (const float*)d_in[6];
    float* out = (float*)d_out;

    const int N = in_sizes[0] / F;
    const int E = in_sizes[1];

    void* msg_ptr = nullptr;
    void* deg_ptr = nullptr;
    cudaGetSymbolAddress(&msg_ptr, g_msg);
    cudaGetSymbolAddress(&deg_ptr, g_deg);

    cudaMemsetAsync(msg_ptr, 0, (size_t)N * F * sizeof(float));
    cudaMemsetAsync(deg_ptr, 0, (size_t)N * sizeof(float));

    transpose_w<<<K2, F>>>(W);

    // one warp per edge, 8 warps (256 threads) per block
    int blocks_e = (E + 7) / 8;
    edge_scatter<<<blocks_e, 256>>>(h, src, dst, E);

    int blocks_n = (N + NT - 1) / NT;
    fused_node<<<blocks_n, 256>>>(h, bias, gamma, beta, out, N);
}

// round 2
// speedup vs baseline: 1.3945x; 1.3945x over previous
#include <cuda_runtime.h>
#include <cstddef>

// Problem constants (shapes fixed for this problem instance)
#define NMAX 100000
#define EMAX 1600000
#define F    128      // in/out feature dim
#define K2   256      // concat dim = 2*F
#define NT   32       // nodes per block in fused kernel

// ---------------- scratch (allocation-free: __device__ globals) ------------
__device__ int   g_cnt[NMAX];      // in-degree (int)
__device__ int   g_off[NMAX];      // CSR row offsets (exclusive scan of cnt)
__device__ int   g_cur[NMAX];      // fill cursors
__device__ int   g_csr[EMAX];      // CSR column indices (src per dst)
__device__ float g_Wt[K2 * F];     // W transposed: Wt[k][j] = W[j][k]

// ---------------- packed f32x2 helpers (sm_100+ FFMA2) ----------------------
__device__ __forceinline__ unsigned long long pack2(float x, float y) {
    unsigned long long r;
    asm("mov.b64 %0, {%1, %2};" : "=l"(r) : "f"(x), "f"(y));
    return r;
}
__device__ __forceinline__ float2 unpack2(unsigned long long v) {
    float2 r;
    asm("mov.b64 {%0, %1}, %2;" : "=f"(r.x), "=f"(r.y) : "l"(v));
    return r;
}
__device__ __forceinline__ unsigned long long fma2(unsigned long long a,
                                                   unsigned long long b,
                                                   unsigned long long c) {
    unsigned long long d;
    asm("fma.rn.f32x2 %0, %1, %2, %3;" : "=l"(d) : "l"(a), "l"(b), "l"(c));
    return d;
}

// ---------------- kernel 1: transpose W (tiny) ------------------------------
__global__ void transpose_w(const float* __restrict__ W) {
    int k = blockIdx.x;     // 0..255
    int j = threadIdx.x;    // 0..127
    g_Wt[k * F + j] = W[j * K2 + k];
}

// ---------------- kernel 2: degree histogram --------------------------------
__global__ void hist_dst(const int* __restrict__ dst, int E) {
    int i = blockIdx.x * blockDim.x + threadIdx.x;
    if (i < E) atomicAdd(&g_cnt[dst[i]], 1);
}

// ---------------- kernel 3: exclusive scan (single block, sequential chunks)-
__global__ void scan_offsets(int N) {
    const int tid = threadIdx.x, lane = tid & 31, wid = tid >> 5;
    __shared__ int wsum[32];
    __shared__ int carry_s;
    if (tid == 0) carry_s = 0;
    __syncthreads();
    for (int base = 0; base < N; base += 1024) {
        int i = base + tid;
        int v = (i < N) ? g_cnt[i] : 0;
        int inc = v;
        #pragma unroll
        for (int o = 1; o < 32; o <<= 1) {
            int t = __shfl_up_sync(0xffffffffu, inc, o);
            if (lane >= o) inc += t;
        }
        if (lane == 31) wsum[wid] = inc;
        __syncthreads();
        if (wid == 0) {
            int s = wsum[lane];
            #pragma unroll
            for (int o = 1; o < 32; o <<= 1) {
                int t = __shfl_up_sync(0xffffffffu, s, o);
                if (lane >= o) s += t;
            }
            wsum[lane] = s;   // inclusive scan of warp totals
        }
        __syncthreads();
        int carry = carry_s;
        int block_excl = (wid > 0) ? wsum[wid - 1] : 0;
        int excl = carry + block_excl + inc - v;
        if (i < N) { g_off[i] = excl; g_cur[i] = excl; }
        int total = wsum[31];
        __syncthreads();
        if (tid == 0) carry_s = carry + total;
        __syncthreads();
    }
}

// ---------------- kernel 4: CSR fill -----------------------------------------
__global__ void fill_csr(const int* __restrict__ src,
                         const int* __restrict__ dst, int E) {
    int i = blockIdx.x * blockDim.x + threadIdx.x;
    if (i < E) {
        int pos = atomicAdd(&g_cur[dst[i]], 1);
        g_csr[pos] = src[i];
    }
}

// ---------------- kernel 5: fused gather-mean + concat-GEMM + LN + ReLU -----
// Block: 256 threads, NT=32 nodes. Warp ty owns nodes n0=4*ty..4*ty+3 fully
// (gather aggregation + GEMM rows + LN via shfl). Lane tx owns cols 4*tx..4*tx+3.
__global__ __launch_bounds__(256)
void fused_node(const float* __restrict__ h,
                const float* __restrict__ bias,
                const float* __restrict__ gamma,
                const float* __restrict__ beta,
                float* __restrict__ out,
                int N) {
    __shared__ float xs[NT][K2];      // 32 KB: concat[h, mean_agg]

    const int tid   = threadIdx.x;
    const int node0 = blockIdx.x * NT;
    const int nval  = min(NT, N - node0);
    const int tx = tid & 31;          // lane
    const int ty = tid >> 5;          // warp
    const int j0 = tx * 4;
    const int n0 = ty * 4;

    // ---- stage h half: xs[n][0:128], vectorized + coalesced ----
    #pragma unroll
    for (int idx = tid; idx < NT * (F / 4); idx += 256) {
        int n = idx >> 5;             // node within tile
        int c = idx & 31;             // float4 index
        float4 v = make_float4(0.f, 0.f, 0.f, 0.f);
        if (n < nval)
            v = *reinterpret_cast<const float4*>(h + (size_t)(node0 + n) * F + c * 4);
        *reinterpret_cast<float4*>(&xs[n][c * 4]) = v;
    }

    // ---- gather-mean half: xs[n][128:256]. Warp per node, lane per 4 cols ----
    #pragma unroll
    for (int ii = 0; ii < 4; ii++) {
        const int n  = n0 + ii;
        const int gn = node0 + n;
        float4 a = make_float4(0.f, 0.f, 0.f, 0.f);
        if (n < nval) {
            const int beg = g_off[gn];
            const int cnt = g_cnt[gn];
            int t = 0;
            for (; t + 2 <= cnt; t += 2) {
                int s0 = __ldg(g_csr + beg + t);
                int s1 = __ldg(g_csr + beg + t + 1);
                float4 v0 = *reinterpret_cast<const float4*>(h + (size_t)s0 * F + j0);
                float4 v1 = *reinterpret_cast<const float4*>(h + (size_t)s1 * F + j0);
                a.x += v0.x + v1.x; a.y += v0.y + v1.y;
                a.z += v0.z + v1.z; a.w += v0.w + v1.w;
            }
            if (t < cnt) {
                int s0 = __ldg(g_csr + beg + t);
                float4 v0 = *reinterpret_cast<const float4*>(h + (size_t)s0 * F + j0);
                a.x += v0.x; a.y += v0.y; a.z += v0.z; a.w += v0.w;
            }
            float r = 1.0f / fmaxf((float)cnt, 1.0f);
            a.x *= r; a.y *= r; a.z *= r; a.w *= r;
        }
        *reinterpret_cast<float4*>(&xs[n][F + j0]) = a;
    }
    __syncthreads();

    // ---- GEMM: acc[i] = x[n0+i][:] . Wt[:, j0..j0+3], packed f32x2 ----
    unsigned long long acc[4][2];
    #pragma unroll
    for (int i = 0; i < 4; i++) { acc[i][0] = 0ull; acc[i][1] = 0ull; }

    #pragma unroll 4
    for (int k = 0; k < K2; k++) {
        const ulonglong2 w = *reinterpret_cast<const ulonglong2*>(g_Wt + k * F + j0);
        #pragma unroll
        for (int i = 0; i < 4; i++) {
            float x = xs[n0 + i][k];
            unsigned long long xp = pack2(x, x);
            acc[i][0] = fma2(xp, w.x, acc[i][0]);
            acc[i][1] = fma2(xp, w.y, acc[i][1]);
        }
    }

    // ---- epilogue: +bias, LayerNorm(128) via warp shfl, affine, ReLU ----
    const float4 bb = *reinterpret_cast<const float4*>(bias  + j0);
    const float4 gg = *reinterpret_cast<const float4*>(gamma + j0);
    const float4 be = *reinterpret_cast<const float4*>(beta  + j0);

    #pragma unroll
    for (int i = 0; i < 4; i++) {
        float2 a0 = unpack2(acc[i][0]);
        float2 a1 = unpack2(acc[i][1]);
        float z0 = a0.x + bb.x;
        float z1 = a0.y + bb.y;
        float z2 = a1.x + bb.z;
        float z3 = a1.y + bb.w;

        float s = z0 + z1 + z2 + z3;
        #pragma unroll
        for (int o = 16; o > 0; o >>= 1) s += __shfl_xor_sync(0xFFFFFFFFu, s, o);
        const float mu = s * (1.0f / 128.0f);

        float d0 = z0 - mu, d1 = z1 - mu, d2 = z2 - mu, d3 = z3 - mu;
        float q = d0 * d0 + d1 * d1 + d2 * d2 + d3 * d3;
        #pragma unroll
        for (int o = 16; o > 0; o >>= 1) q += __shfl_xor_sync(0xFFFFFFFFu, q, o);
        const float inv = rsqrtf(q * (1.0f / 128.0f) + 1e-5f);

        float4 r;
        r.x = fmaxf(d0 * inv * gg.x + be.x, 0.0f);
        r.y = fmaxf(d1 * inv * gg.y + be.y, 0.0f);
        r.z = fmaxf(d2 * inv * gg.z + be.z, 0.0f);
        r.w = fmaxf(d3 * inv * gg.w + be.w, 0.0f);

        if (n0 + i < nval)
            *reinterpret_cast<float4*>(out + (size_t)(node0 + n0 + i) * F + j0) = r;
    }
}

// ---------------- launch ----------------------------------------------------
extern "C" void kernel_launch(void* const* d_in, const int* in_sizes, int n_in,
                              void* d_out, int out_size) {
    const float* h     = (const float*)d_in[0];
    const int*   src   = (const int*)  d_in[1];
    const int*   dst   = (const int*)  d_in[2];
    const float* W     = (const float*)d_in[3];
    const float* bias  = (const float*)d_in[4];
    const float* gamma = (const float*)d_in[5];
    const float* beta  = (const float*)d_in[6];
    float* out = (float*)d_out;

    const int N = in_sizes[0] / F;
    const int E = in_sizes[1];

    void* cnt_ptr = nullptr;
    cudaGetSymbolAddress(&cnt_ptr, g_cnt);
    cudaMemsetAsync(cnt_ptr, 0, (size_t)N * sizeof(int));

    transpose_w<<<K2, F>>>(W);
    hist_dst<<<(E + 255) / 256, 256>>>(dst, E);
    scan_offsets<<<1, 1024>>>(N);
    fill_csr<<<(E + 255) / 256, 256>>>(src, dst, E);

    int blocks_n = (N + NT - 1) / NT;
    fused_node<<<blocks_n, 256>>>(h, bias, gamma, beta, out, N);
}

// round 3
// speedup vs baseline: 1.5201x; 1.0901x over previous
#include <cuda_runtime.h>
#include <cstddef>

#define NMAX 100000
#define EMAX 1600000
#define F    128      // feature dim
#define K2   256      // concat dim
#define NT   64       // nodes per fused block
#define NPAIR 32      // NT/2 node pairs
#define PPAD  33      // padded pair stride
#define SCAN_CHUNK 1024
#define NBLK_SCAN  ((NMAX + SCAN_CHUNK - 1) / SCAN_CHUNK)   // 98

// ---------------- scratch ----------------------------------------------------
__device__ int   g_cnt[NMAX];
__device__ int   g_off[NMAX];
__device__ int   g_cur[NMAX];
__device__ int   g_csr[EMAX];
__device__ float g_Wtd[K2 * 2 * F];   // [k][2j]=[k][2j+1]=W[j][k]  (256 KB)
__device__ int   g_bsum[NBLK_SCAN];
__device__ int   g_bbase[NBLK_SCAN];

// ---------------- f32x2 helpers ----------------------------------------------
__device__ __forceinline__ unsigned long long fma2(unsigned long long a,
                                                   unsigned long long b,
                                                   unsigned long long c) {
    unsigned long long d;
    asm("fma.rn.f32x2 %0, %1, %2, %3;" : "=l"(d) : "l"(a), "l"(b), "l"(c));
    return d;
}
__device__ __forceinline__ float2 unpack2(unsigned long long v) {
    float2 r;
    asm("mov.b64 {%0, %1}, %2;" : "=f"(r.x), "=f"(r.y) : "l"(v));
    return r;
}

// ---------------- kernel: transpose + duplicate W ----------------------------
__global__ void transpose_w(const float* __restrict__ W) {
    int k = blockIdx.x;     // 0..255
    int j = threadIdx.x;    // 0..127
    float v = W[j * K2 + k];
    float2* p = reinterpret_cast<float2*>(g_Wtd + k * 2 * F);
    p[j] = make_float2(v, v);
}

// ---------------- kernel: degree histogram -----------------------------------
__global__ void hist_dst(const int* __restrict__ dst, int E) {
    int i = blockIdx.x * blockDim.x + threadIdx.x;
    if (i < E) atomicAdd(&g_cnt[dst[i]], 1);
}

// ---------------- parallel exclusive scan (3 kernels) -------------------------
__global__ void scan_part1(int N) {      // block sums
    const int b = blockIdx.x, tid = threadIdx.x;
    int i0 = b * SCAN_CHUNK + tid * 4;
    int s = 0;
    #pragma unroll
    for (int q = 0; q < 4; q++) { int i = i0 + q; if (i < N) s += g_cnt[i]; }
    #pragma unroll
    for (int o = 16; o > 0; o >>= 1) s += __shfl_xor_sync(0xffffffffu, s, o);
    __shared__ int ws[8];
    if ((tid & 31) == 0) ws[tid >> 5] = s;
    __syncthreads();
    if (tid == 0) {
        int t = 0;
        #pragma unroll
        for (int w = 0; w < 8; w++) t += ws[w];
        g_bsum[b] = t;
    }
}
__global__ void scan_part2(int nb) {     // scan block sums -> exclusive bases
    const int tid = threadIdx.x, lane = tid & 31, wid = tid >> 5;
    int x = (tid < nb) ? g_bsum[tid] : 0;
    int inc = x;
    #pragma unroll
    for (int o = 1; o < 32; o <<= 1) {
        int t = __shfl_up_sync(0xffffffffu, inc, o);
        if (lane >= o) inc += t;
    }
    __shared__ int ws[4];
    if (lane == 31) ws[wid] = inc;
    __syncthreads();
    int wbase = 0;
    for (int w = 0; w < wid; w++) wbase += ws[w];
    if (tid < nb) g_bbase[tid] = wbase + inc - x;
}
__global__ void scan_part3(int N) {      // local scan + base -> g_off, g_cur
    const int b = blockIdx.x, tid = threadIdx.x;
    const int lane = tid & 31, wid = tid >> 5;
    int i0 = b * SCAN_CHUNK + tid * 4;
    int v[4];
    #pragma unroll
    for (int q = 0; q < 4; q++) { int i = i0 + q; v[q] = (i < N) ? g_cnt[i] : 0; }
    int s = v[0] + v[1] + v[2] + v[3];
    int inc = s;
    #pragma unroll
    for (int o = 1; o < 32; o <<= 1) {
        int t = __shfl_up_sync(0xffffffffu, inc, o);
        if (lane >= o) inc += t;
    }
    __shared__ int ws[8], wse[8];
    if (lane == 31) ws[wid] = inc;
    __syncthreads();
    if (tid == 0) {
        int r = 0;
        #pragma unroll
        for (int w = 0; w < 8; w++) { wse[w] = r; r += ws[w]; }
    }
    __syncthreads();
    int run = g_bbase[b] + wse[wid] + (inc - s);
    #pragma unroll
    for (int q = 0; q < 4; q++) {
        int i = i0 + q;
        if (i < N) { g_off[i] = run; g_cur[i] = run; }
        run += v[q];
    }
}

// ---------------- kernel: CSR fill --------------------------------------------
__global__ void fill_csr(const int* __restrict__ src,
                         const int* __restrict__ dst, int E) {
    int i = blockIdx.x * blockDim.x + threadIdx.x;
    if (i < E) {
        int pos = atomicAdd(&g_cur[dst[i]], 1);
        g_csr[pos] = src[i];
    }
}

// ---------------- LN + affine + ReLU + store helper ---------------------------
__device__ __forceinline__ void ln_store(float z0, float z1, float z2, float z3,
                                         const float4 gg, const float4 be,
                                         bool valid, float* ptr) {
    float s = z0 + z1 + z2 + z3;
    #pragma unroll
    for (int o = 16; o > 0; o >>= 1) s += __shfl_xor_sync(0xffffffffu, s, o);
    const float mu = s * (1.0f / 128.0f);
    float d0 = z0 - mu, d1 = z1 - mu, d2 = z2 - mu, d3 = z3 - mu;
    float q = d0 * d0 + d1 * d1 + d2 * d2 + d3 * d3;
    #pragma unroll
    for (int o = 16; o > 0; o >>= 1) q += __shfl_xor_sync(0xffffffffu, q, o);
    const float inv = rsqrtf(q * (1.0f / 128.0f) + 1e-5f);
    if (valid) {
        float4 r;
        r.x = fmaxf(d0 * inv * gg.x + be.x, 0.0f);
        r.y = fmaxf(d1 * inv * gg.y + be.y, 0.0f);
        r.z = fmaxf(d2 * inv * gg.z + be.z, 0.0f);
        r.w = fmaxf(d3 * inv * gg.w + be.w, 0.0f);
        *reinterpret_cast<float4*>(ptr) = r;
    }
}

// ---------------- fused: gather-mean + concat-GEMM(f32x2) + LN + ReLU ---------
// 128 threads = 4 warps. Warp w owns 16 nodes (8 pairs p0=8w..8w+7).
// Lane owns cols j0=4*lane..j0+3. xsp[k][pair] = packed (x[2p][k], x[2p+1][k]).
__global__ __launch_bounds__(128, 3)
void fused_node(const float* __restrict__ h,
                const float* __restrict__ bias,
                const float* __restrict__ gamma,
                const float* __restrict__ beta,
                float* __restrict__ out,
                int N) {
    extern __shared__ unsigned long long xsp[];   // [K2][PPAD] = 67584 B
    const int tid   = threadIdx.x;
    const int lane  = tid & 31;
    const int warp  = tid >> 5;
    const int node0 = blockIdx.x * NT;
    const int nval  = min(NT, N - node0);
    const int j0    = lane * 4;
    const int p0    = warp * 8;

    // ---- stage h half (k in [0,128)) ----
    #pragma unroll
    for (int idx = tid; idx < NT * (F / 4); idx += 128) {
        int n = idx >> 5;            // node 0..63
        int c = idx & 31;            // float4 index
        float4 v = make_float4(0.f, 0.f, 0.f, 0.f);
        if (n < nval)
            v = *reinterpret_cast<const float4*>(h + (size_t)(node0 + n) * F + c * 4);
        float* base = reinterpret_cast<float*>(xsp);
        int half = n & 1, pair = n >> 1;
        base[((c * 4 + 0) * PPAD + pair) * 2 + half] = v.x;
        base[((c * 4 + 1) * PPAD + pair) * 2 + half] = v.y;
        base[((c * 4 + 2) * PPAD + pair) * 2 + half] = v.z;
        base[((c * 4 + 3) * PPAD + pair) * 2 + half] = v.w;
    }

    // ---- gather-mean half (k in [128,256)): warp gathers its 16 nodes ----
    for (int nn = warp * 16; nn < warp * 16 + 16; nn++) {
        float4 a = make_float4(0.f, 0.f, 0.f, 0.f);
        if (nn < nval) {
            const int gn  = node0 + nn;
            const int beg = g_off[gn];
            const int cnt = g_cnt[gn];
            int t = 0;
            for (; t + 4 <= cnt; t += 4) {
                int s0 = __ldg(g_csr + beg + t);
                int s1 = __ldg(g_csr + beg + t + 1);
                int s2 = __ldg(g_csr + beg + t + 2);
                int s3 = __ldg(g_csr + beg + t + 3);
                float4 v0 = *reinterpret_cast<const float4*>(h + (size_t)s0 * F + j0);
                float4 v1 = *reinterpret_cast<const float4*>(h + (size_t)s1 * F + j0);
                float4 v2 = *reinterpret_cast<const float4*>(h + (size_t)s2 * F + j0);
                float4 v3 = *reinterpret_cast<const float4*>(h + (size_t)s3 * F + j0);
                a.x += (v0.x + v1.x) + (v2.x + v3.x);
                a.y += (v0.y + v1.y) + (v2.y + v3.y);
                a.z += (v0.z + v1.z) + (v2.z + v3.z);
                a.w += (v0.w + v1.w) + (v2.w + v3.w);
            }
            for (; t < cnt; t++) {
                int s0 = __ldg(g_csr + beg + t);
                float4 v0 = *reinterpret_cast<const float4*>(h + (size_t)s0 * F + j0);
                a.x += v0.x; a.y += v0.y; a.z += v0.z; a.w += v0.w;
            }
            float r = 1.0f / fmaxf((float)cnt, 1.0f);
            a.x *= r; a.y *= r; a.z *= r; a.w *= r;
        }
        float* base = reinterpret_cast<float*>(xsp);
        int half = nn & 1, pair = nn >> 1;
        base[((F + j0 + 0) * PPAD + pair) * 2 + half] = a.x;
        base[((F + j0 + 1) * PPAD + pair) * 2 + half] = a.y;
        base[((F + j0 + 2) * PPAD + pair) * 2 + half] = a.z;
        base[((F + j0 + 3) * PPAD + pair) * 2 + half] = a.w;
    }
    __syncthreads();

    // ---- GEMM: 16 nodes x 4 cols per thread, all f32x2 over node pairs ----
    unsigned long long acc[8][4];
    #pragma unroll
    for (int i = 0; i < 8; i++)
        #pragma unroll
        for (int c = 0; c < 4; c++) acc[i][c] = 0ull;

    const float* wbase = g_Wtd + 8 * lane;   // duplicated cols j0..j0+3
    #pragma unroll 4
    for (int k = 0; k < K2; k++) {
        const ulonglong2 wa = *reinterpret_cast<const ulonglong2*>(wbase + (size_t)k * 2 * F);
        const ulonglong2 wb = *reinterpret_cast<const ulonglong2*>(wbase + (size_t)k * 2 * F + 4);
        const unsigned long long* xrow = xsp + (size_t)k * PPAD + p0;
        #pragma unroll
        for (int i = 0; i < 8; i++) {
            unsigned long long x = xrow[i];
            acc[i][0] = fma2(x, wa.x, acc[i][0]);
            acc[i][1] = fma2(x, wa.y, acc[i][1]);
            acc[i][2] = fma2(x, wb.x, acc[i][2]);
            acc[i][3] = fma2(x, wb.y, acc[i][3]);
        }
    }

    // ---- epilogue ----
    const float4 bb = *reinterpret_cast<const float4*>(bias  + j0);
    const float4 gg = *reinterpret_cast<const float4*>(gamma + j0);
    const float4 be = *reinterpret_cast<const float4*>(beta  + j0);

    #pragma unroll
    for (int i = 0; i < 8; i++) {
        float2 u0 = unpack2(acc[i][0]);
        float2 u1 = unpack2(acc[i][1]);
        float2 u2 = unpack2(acc[i][2]);
        float2 u3 = unpack2(acc[i][3]);
        int nn = 2 * (p0 + i);                 // even node of the pair
        ln_store(u0.x + bb.x, u1.x + bb.y, u2.x + bb.z, u3.x + bb.w,
                 gg, be, nn < nval,
                 out + (size_t)(node0 + nn) * F + j0);
        ln_store(u0.y + bb.x, u1.y + bb.y, u2.y + bb.z, u3.y + bb.w,
                 gg, be, nn + 1 < nval,
                 out + (size_t)(node0 + nn + 1) * F + j0);
    }
}

// ---------------- launch -------------------------------------------------------
extern "C" void kernel_launch(void* const* d_in, const int* in_sizes, int n_in,
                              void* d_out, int out_size) {
    const float* h     = (const float*)d_in[0];
    const int*   src   = (const int*)  d_in[1];
    const int*   dst   = (const int*)  d_in[2];
    const float* W     = (const float*)d_in[3];
    const float* bias  = (const float*)d_in[4];
    const float* gamma = (const float*)d_in[5];
    const float* beta  = (const float*)d_in[6];
    float* out = (float*)d_out;

    const int N = in_sizes[0] / F;
    const int E = in_sizes[1];

    void* cnt_ptr = nullptr;
    cudaGetSymbolAddress(&cnt_ptr, g_cnt);
    cudaMemsetAsync(cnt_ptr, 0, (size_t)N * sizeof(int));

    transpose_w<<<K2, F>>>(W);
    hist_dst<<<(E + 255) / 256, 256>>>(dst, E);

    int nb = (N + SCAN_CHUNK - 1) / SCAN_CHUNK;
    scan_part1<<<nb, 256>>>(N);
    scan_part2<<<1, 128>>>(nb);
    scan_part3<<<nb, 256>>>(N);

    fill_csr<<<(E + 255) / 256, 256>>>(src, dst, E);

    static int smem_set = 0;
    const int smem_bytes = K2 * PPAD * sizeof(unsigned long long);  // 67584
    if (!smem_set) {
        cudaFuncSetAttribute(fused_node, cudaFuncAttributeMaxDynamicSharedMemorySize,
                             smem_bytes);
        smem_set = 1;
    }
    int blocks_n = (N + NT - 1) / NT;
    fused_node<<<blocks_n, 128, smem_bytes>>>(h, bias, gamma, beta, out, N);
}